// round 5
// baseline (speedup 1.0000x reference)
#include <cuda_runtime.h>
#include <cuda_fp16.h>
#include <cstdint>

#define Bb 2
#define Nn 2048
#define Hh 8
#define DHd 64
#define Kk 32
#define SCALEf 0.125f
#define NEG_HUGE (-3.402823466e+38f)

// ---------------- mma / ldmatrix helpers ----------------
__device__ __forceinline__ void ldsm4(uint32_t& r0, uint32_t& r1, uint32_t& r2,
                                      uint32_t& r3, uint32_t addr) {
    asm volatile("ldmatrix.sync.aligned.m8n8.x4.shared.b16 {%0,%1,%2,%3}, [%4];"
                 : "=r"(r0), "=r"(r1), "=r"(r2), "=r"(r3) : "r"(addr));
}
__device__ __forceinline__ void ldsm4t(uint32_t& r0, uint32_t& r1, uint32_t& r2,
                                       uint32_t& r3, uint32_t addr) {
    asm volatile("ldmatrix.sync.aligned.m8n8.x4.trans.shared.b16 {%0,%1,%2,%3}, [%4];"
                 : "=r"(r0), "=r"(r1), "=r"(r2), "=r"(r3) : "r"(addr));
}
__device__ __forceinline__ void mma_f16(float* d, const uint32_t* a,
                                        uint32_t b0, uint32_t b1) {
    asm volatile(
        "mma.sync.aligned.m16n8k16.row.col.f32.f16.f16.f32 "
        "{%0,%1,%2,%3}, {%4,%5,%6,%7}, {%8,%9}, {%0,%1,%2,%3};"
        : "+f"(d[0]), "+f"(d[1]), "+f"(d[2]), "+f"(d[3])
        : "r"(a[0]), "r"(a[1]), "r"(a[2]), "r"(a[3]), "r"(b0), "r"(b1));
}
__device__ __forceinline__ uint32_t h2u(float x, float y) {
    __half2 h = __floats2half2_rn(x, y);
    return *(uint32_t*)&h;
}

// ---------------- scratch ----------------
__device__ __half g_q[Bb * Nn * (Hh * DHd)];
__device__ __half g_kv[Bb * Nn * (2 * DHd)];
__device__ float g_local[Bb * Hh * Nn * DHd];
__device__ float g_memv[Bb * Hh * Nn * DHd];
__device__ unsigned char g_mask[Bb * Hh * Nn * Kk];
__device__ int g_mask_mode;

// ---------------- mask dtype detection / expansion ----------------
__global__ void detect_mask_kernel(const unsigned int* __restrict__ raw) {
    __shared__ int cf, ch;
    if (threadIdx.x == 0) { cf = 0; ch = 0; }
    __syncthreads();
    int lf = 0, lh = 0;
    for (int idx = threadIdx.x; idx < 4096; idx += 256) {
        unsigned w = raw[idx];
        if (w == 0x3f800000u) lf++;
        if (w & 0xFFFFFF00u) lh++;
    }
    atomicAdd(&cf, lf);
    atomicAdd(&ch, lh);
    __syncthreads();
    if (threadIdx.x == 0) {
        int mode;
        if (cf > 64) mode = 2;
        else if (ch > 64) mode = 0;
        else mode = 1;
        g_mask_mode = mode;
    }
}

__global__ void expand_mask_kernel(const void* __restrict__ raw, int n) {
    int idx = blockIdx.x * blockDim.x + threadIdx.x;
    if (idx >= n) return;
    int mode = g_mask_mode;
    unsigned char v;
    if (mode == 0)      v = ((const unsigned char*)raw)[idx] != 0;
    else if (mode == 1) v = ((const int*)raw)[idx] != 0;
    else                v = (((const float*)raw)[idx] != 0.0f);
    g_mask[idx] = v;
}

// ---------------- fp16 MMA GEMM: tile 128x64, BK=32, 256 threads (8 warps) ----------------
// COMBINE: A is synthesized on the fly as gate-combined local/memv (fp32 -> fp16).
template <bool OUT_HALF, bool COMBINE>
__global__ void __launch_bounds__(256) gemm_kernel(
    const float* __restrict__ A,
    const float* __restrict__ Amem, const float* __restrict__ gatep,
    const float* __restrict__ B1, void* __restrict__ C1, int ldb1, int ldc1,
    const float* __restrict__ B2, void* __restrict__ C2, int ldb2, int ldc2,
    int nb1, const float* __restrict__ bias, int Kd)
{
    __shared__ __half As[128 * 40];  // [r][k], stride 40 halfs
    __shared__ __half Bs[32 * 72];   // [k][n], stride 72 halfs
    int tid = threadIdx.x;
    int warp = tid >> 5, lane = tid & 31;
    int lg = lane >> 2, lt = lane & 3;
    int rowBase = blockIdx.y * 128;
    const float* Bm; void* C; int ldb, ldc, colBase;
    bool hasBias;
    if ((int)blockIdx.x < nb1) {
        Bm = B1; C = C1; ldb = ldb1; ldc = ldc1; colBase = blockIdx.x * 64;
        hasBias = false;
    } else {
        Bm = B2; C = C2; ldb = ldb2; ldc = ldc2; colBase = (blockIdx.x - nb1) * 64;
        hasBias = (bias != nullptr);
    }

    uint32_t asb = (uint32_t)__cvta_generic_to_shared(As);
    uint32_t bsb = (uint32_t)__cvta_generic_to_shared(Bs);
    int a_row = (lane & 7) + (lane & 8);
    int a_cb = (lane & 16) >> 1;

    float acc[8][4];
#pragma unroll
    for (int j = 0; j < 8; j++)
#pragma unroll
        for (int q = 0; q < 4; q++) acc[j][q] = 0.f;

    int r0 = warp * 16;

    for (int k0 = 0; k0 < Kd; k0 += 32) {
        // stage A 128x32 -> fp16
#pragma unroll
        for (int rep = 0; rep < 4; rep++) {
            int r = (tid >> 3) + rep * 32;
            int kq = (tid & 7) * 4;
            float4 v;
            if (COMBINE) {
                int R = rowBase + r;
                int b = R >> 11, i = R & 2047;
                int c = k0 + kq;
                int h = c >> 6, d = c & 63;
                size_t idx = (((size_t)(b * 8 + h) * 2048 + i) * 64 + d);
                float4 lv = *(const float4*)&A[idx];
                float4 mv = *(const float4*)&Amem[idx];
                float g = 1.f / (1.f + __expf(-__ldg(&gatep[h])));
                v.x = lv.x * g + mv.x * (1.f - g);
                v.y = lv.y * g + mv.y * (1.f - g);
                v.z = lv.z * g + mv.z * (1.f - g);
                v.w = lv.w * g + mv.w * (1.f - g);
            } else {
                v = *(const float4*)&A[(size_t)(rowBase + r) * Kd + k0 + kq];
            }
            uint2 u = {h2u(v.x, v.y), h2u(v.z, v.w)};
            *(uint2*)&As[r * 40 + kq] = u;
        }
        // stage B 32x64 -> fp16
#pragma unroll
        for (int rep = 0; rep < 2; rep++) {
            int kk = (tid >> 4) + rep * 16;
            int c4 = (tid & 15) * 4;
            float4 v = *(const float4*)&Bm[(size_t)(k0 + kk) * ldb + colBase + c4];
            uint2 u = {h2u(v.x, v.y), h2u(v.z, v.w)};
            *(uint2*)&Bs[kk * 72 + c4] = u;
        }
        __syncthreads();
#pragma unroll
        for (int kc = 0; kc < 2; kc++) {
            uint32_t a[4];
            ldsm4(a[0], a[1], a[2], a[3],
                  asb + ((r0 + a_row) * 40 + kc * 16 + a_cb) * 2);
#pragma unroll
            for (int jn2 = 0; jn2 < 4; jn2++) {
                uint32_t b0, b1, b2, b3;
                ldsm4t(b0, b1, b2, b3,
                       bsb + ((kc * 16 + a_row) * 72 + jn2 * 16 + a_cb) * 2);
                mma_f16(acc[2 * jn2], a, b0, b1);
                mma_f16(acc[2 * jn2 + 1], a, b2, b3);
            }
        }
        __syncthreads();
    }

#pragma unroll
    for (int jn = 0; jn < 8; jn++) {
        int col = colBase + jn * 8 + 2 * lt;
        float b0 = 0.f, b1 = 0.f;
        if (hasBias) { b0 = bias[col]; b1 = bias[col + 1]; }
        size_t off0 = (size_t)(rowBase + r0 + lg) * ldc + col;
        size_t off1 = (size_t)(rowBase + r0 + lg + 8) * ldc + col;
        if (OUT_HALF) {
            *(__half2*)&((__half*)C)[off0] =
                __floats2half2_rn(acc[jn][0] + b0, acc[jn][1] + b1);
            *(__half2*)&((__half*)C)[off1] =
                __floats2half2_rn(acc[jn][2] + b0, acc[jn][3] + b1);
        } else {
            float2 w0 = {acc[jn][0] + b0, acc[jn][1] + b1};
            float2 w1 = {acc[jn][2] + b0, acc[jn][3] + b1};
            *(float2*)&((float*)C)[off0] = w0;
            *(float2*)&((float*)C)[off1] = w1;
        }
    }
}

// ---------------- flash body (blocks 0..127 of fused kernel) ----------------
__device__ __forceinline__ void flash_body(
    int px, int bh,
    const __half* __restrict__ q, const __half* __restrict__ kv,
    float* __restrict__ localOut)
{
    __shared__ __half Qs[128 * 72];
    __shared__ __half Ks[64 * 72];
    __shared__ __half Vs[64 * 72];

    int tid = threadIdx.x;
    int warp = tid >> 5, lane = tid & 31;
    int lg = lane >> 2, lt = lane & 3;
    int b = bh >> 3, h = bh & 7;

    uint32_t qsb = (uint32_t)__cvta_generic_to_shared(Qs);
    uint32_t ksb = (uint32_t)__cvta_generic_to_shared(Ks);
    uint32_t vsb = (uint32_t)__cvta_generic_to_shared(Vs);
    int a_row = (lane & 7) + (lane & 8);
    int a_cb = (lane & 16) >> 1;
    int k_row = (lane & 7) + ((lane & 16) >> 1);
    int k_cb = (lane & 8);

    int r0 = warp * 16;

    for (int half_i = 0; half_i < 2; half_i++) {
        int qb = half_i ? (15 - px) : px;
        int i0 = qb * 128;

#pragma unroll
        for (int rep = 0; rep < 4; rep++) {
            int idx = tid + rep * 256;
            int r = idx >> 3;
            int c8 = (idx & 7) * 8;
            *(uint4*)&Qs[r * 72 + c8] =
                *(const uint4*)&q[(size_t)(b * Nn + i0 + r) * 512 + h * 64 + c8];
        }
        __syncthreads();

        uint32_t qa[4][4];
#pragma unroll
        for (int kc = 0; kc < 4; kc++)
            ldsm4(qa[kc][0], qa[kc][1], qa[kc][2], qa[kc][3],
                  qsb + ((r0 + a_row) * 72 + kc * 16 + a_cb) * 2);

        float o[8][4];
#pragma unroll
        for (int j = 0; j < 8; j++)
#pragma unroll
            for (int qq = 0; qq < 4; qq++) o[j][qq] = 0.f;
        float m_lo = NEG_HUGE, m_hi = NEG_HUGE, l_lo = 0.f, l_hi = 0.f;

        int row_lo = i0 + r0 + lg;
        int row_hi = row_lo + 8;
        int numJ = 2 * qb + 2;

        for (int jb = 0; jb < numJ; jb++) {
            int j0 = jb * 64;
            __syncthreads();
#pragma unroll
            for (int rep = 0; rep < 4; rep++) {
                int idx = tid + rep * 256;
                int c = idx >> 4;
                int q8 = (idx & 15) * 8;
                uint4 v = *(const uint4*)&kv[(size_t)(b * Nn + j0 + c) * 128 + q8];
                if (q8 < 64) *(uint4*)&Ks[c * 72 + q8] = v;
                else         *(uint4*)&Vs[c * 72 + q8 - 64] = v;
            }
            __syncthreads();

            float sacc[8][4];
#pragma unroll
            for (int j = 0; j < 8; j++)
#pragma unroll
                for (int qq = 0; qq < 4; qq++) sacc[j][qq] = 0.f;
#pragma unroll
            for (int kc = 0; kc < 4; kc++) {
#pragma unroll
                for (int jn2 = 0; jn2 < 4; jn2++) {
                    uint32_t b0, b1, b2, b3;
                    ldsm4(b0, b1, b2, b3,
                          ksb + ((jn2 * 16 + k_row) * 72 + kc * 16 + k_cb) * 2);
                    mma_f16(sacc[2 * jn2], qa[kc], b0, b1);
                    mma_f16(sacc[2 * jn2 + 1], qa[kc], b2, b3);
                }
            }

            if (jb >= 2 * qb) {
#pragma unroll
                for (int jn = 0; jn < 8; jn++) {
                    int c0 = j0 + jn * 8 + 2 * lt;
                    if (c0 > row_lo) sacc[jn][0] = NEG_HUGE;
                    if (c0 + 1 > row_lo) sacc[jn][1] = NEG_HUGE;
                    if (c0 > row_hi) sacc[jn][2] = NEG_HUGE;
                    if (c0 + 1 > row_hi) sacc[jn][3] = NEG_HUGE;
                }
            }

            float mx_lo = NEG_HUGE, mx_hi = NEG_HUGE;
#pragma unroll
            for (int jn = 0; jn < 8; jn++) {
                mx_lo = fmaxf(mx_lo, fmaxf(sacc[jn][0], sacc[jn][1]));
                mx_hi = fmaxf(mx_hi, fmaxf(sacc[jn][2], sacc[jn][3]));
            }
            mx_lo = fmaxf(mx_lo, __shfl_xor_sync(0xffffffffu, mx_lo, 1));
            mx_lo = fmaxf(mx_lo, __shfl_xor_sync(0xffffffffu, mx_lo, 2));
            mx_hi = fmaxf(mx_hi, __shfl_xor_sync(0xffffffffu, mx_hi, 1));
            mx_hi = fmaxf(mx_hi, __shfl_xor_sync(0xffffffffu, mx_hi, 2));
            float nm_lo = fmaxf(m_lo, mx_lo);
            float nm_hi = fmaxf(m_hi, mx_hi);
            float al_lo = __expf((m_lo - nm_lo) * SCALEf);
            float al_hi = __expf((m_hi - nm_hi) * SCALEf);
            m_lo = nm_lo; m_hi = nm_hi;

            uint32_t pa[4][4];
            float rs_lo = 0.f, rs_hi = 0.f;
#pragma unroll
            for (int jn = 0; jn < 8; jn++) {
                float p0 = __expf((sacc[jn][0] - nm_lo) * SCALEf);
                float p1 = __expf((sacc[jn][1] - nm_lo) * SCALEf);
                float p2 = __expf((sacc[jn][2] - nm_hi) * SCALEf);
                float p3 = __expf((sacc[jn][3] - nm_hi) * SCALEf);
                rs_lo += p0 + p1;
                rs_hi += p2 + p3;
                int kc = jn >> 1;
                int hi = (jn & 1) ? 2 : 0;
                pa[kc][hi] = h2u(p0, p1);
                pa[kc][hi + 1] = h2u(p2, p3);
                o[jn][0] *= al_lo; o[jn][1] *= al_lo;
                o[jn][2] *= al_hi; o[jn][3] *= al_hi;
            }
            rs_lo += __shfl_xor_sync(0xffffffffu, rs_lo, 1);
            rs_lo += __shfl_xor_sync(0xffffffffu, rs_lo, 2);
            rs_hi += __shfl_xor_sync(0xffffffffu, rs_hi, 1);
            rs_hi += __shfl_xor_sync(0xffffffffu, rs_hi, 2);
            l_lo = l_lo * al_lo + rs_lo;
            l_hi = l_hi * al_hi + rs_hi;

#pragma unroll
            for (int kc = 0; kc < 4; kc++) {
#pragma unroll
                for (int dn2 = 0; dn2 < 4; dn2++) {
                    uint32_t b0, b1, b2, b3;
                    ldsm4t(b0, b1, b2, b3,
                           vsb + ((kc * 16 + a_row) * 72 + dn2 * 16 + a_cb) * 2);
                    mma_f16(o[2 * dn2], pa[kc], b0, b1);
                    mma_f16(o[2 * dn2 + 1], pa[kc], b2, b3);
                }
            }
        }

        float inv_lo = 1.f / l_lo, inv_hi = 1.f / l_hi;
#pragma unroll
        for (int jn = 0; jn < 8; jn++) {
            int col = jn * 8 + 2 * lt;
            float2 w0 = {o[jn][0] * inv_lo, o[jn][1] * inv_lo};
            float2 w1 = {o[jn][2] * inv_hi, o[jn][3] * inv_hi};
            *(float2*)&localOut[((size_t)bh * Nn + row_lo) * 64 + col] = w0;
            *(float2*)&localOut[((size_t)bh * Nn + row_hi) * 64 + col] = w1;
        }
        __syncthreads();
    }
}

// ---------------- mem body (blocks 128.. of fused kernel) ----------------
__device__ __forceinline__ void mem_body(
    int mb,
    const __half* __restrict__ q, const float* __restrict__ memkv,
    const float* __restrict__ nullk, const float* __restrict__ nullv,
    float* __restrict__ memvOut)
{
    int gw = mb * 8 + ((int)threadIdx.x >> 5);
    int lane = threadIdx.x & 31;
    int b = gw >> 14;
    int rem = gw & 16383;
    int h = rem >> 11;
    int i = rem & 2047;

    const __half* qp = &q[(size_t)(b * Nn + i) * 512 + h * 64];
    float q0 = __half2float(qp[lane]), q1 = __half2float(qp[lane + 32]);

    float s = q0 * nullk[lane] + q1 * nullk[lane + 32];
#pragma unroll
    for (int off = 16; off >= 1; off >>= 1) s += __shfl_xor_sync(0xffffffffu, s, off);
    s *= SCALEf;
    float m = s, ls = 1.f;
    float a0 = nullv[lane], a1 = nullv[lane + 32];

    size_t base = (size_t)(b * Hh + h) * Nn + i;
    const unsigned char* mp = &g_mask[base * Kk];
    unsigned mbits = __ballot_sync(0xffffffffu, mp[lane] != 0);
    const float* kvp = &memkv[base * (size_t)(Kk * 2 * DHd)];

    for (int kk = 0; kk < Kk; kk++) {
        if (!((mbits >> kk) & 1u)) continue;
        const float* kp = kvp + (size_t)kk * 128;
        float ss = q0 * __ldcs(&kp[lane]) + q1 * __ldcs(&kp[lane + 32]);
#pragma unroll
        for (int off = 16; off >= 1; off >>= 1) ss += __shfl_xor_sync(0xffffffffu, ss, off);
        ss *= SCALEf;
        float nm = fmaxf(m, ss);
        float al = __expf(m - nm);
        float p = __expf(ss - nm);
        m = nm;
        ls = ls * al + p;
        a0 = a0 * al + p * __ldcs(&kp[64 + lane]);
        a1 = a1 * al + p * __ldcs(&kp[96 + lane]);
    }
    float inv = 1.f / ls;
    float* mv = &memvOut[base * DHd];
    mv[lane] = a0 * inv;
    mv[lane + 32] = a1 * inv;
}

// ---------------- fused flash + mem-attention kernel ----------------
__global__ void __launch_bounds__(256) fused_attn_kernel(
    const __half* __restrict__ q, const __half* __restrict__ kv,
    float* __restrict__ localOut,
    const float* __restrict__ memkv,
    const float* __restrict__ nullk, const float* __restrict__ nullv,
    float* __restrict__ memvOut)
{
    int bid = blockIdx.x;
    if (bid < 128) {
        flash_body(bid & 7, bid >> 3, q, kv, localOut);
    } else {
        mem_body(bid - 128, q, memkv, nullk, nullv, memvOut);
    }
}

// ---------------- launch ----------------
extern "C" void kernel_launch(void* const* d_in, const int* in_sizes, int n_in,
                              void* d_out, int out_size) {
    const float* x      = (const float*)d_in[0];
    const float* mem_kv = (const float*)d_in[1];
    const void*  m_mask = d_in[2];
    const float* Wq     = (const float*)d_in[3];
    const float* Wkv    = (const float*)d_in[4];
    const float* Wo     = (const float*)d_in[5];
    const float* bo     = (const float*)d_in[6];
    const float* null_k = (const float*)d_in[7];
    const float* null_v = (const float*)d_in[8];
    const float* gate   = (const float*)d_in[9];
    float* out = (float*)d_out;

    __half* q_buf;    cudaGetSymbolAddress((void**)&q_buf, g_q);
    __half* kv_buf;   cudaGetSymbolAddress((void**)&kv_buf, g_kv);
    float* local_buf; cudaGetSymbolAddress((void**)&local_buf, g_local);
    float* memv_buf;  cudaGetSymbolAddress((void**)&memv_buf, g_memv);

    detect_mask_kernel<<<1, 256>>>((const unsigned int*)m_mask);
    expand_mask_kernel<<<(Bb * Hh * Nn * Kk + 255) / 256, 256>>>(m_mask,
                                                                 Bb * Hh * Nn * Kk);

    // fused q + kv projection (fp16 outputs): tiles 0..7 -> Wq/g_q, 8..9 -> Wkv/g_kv
    gemm_kernel<true, false><<<dim3(10, (Bb * Nn) / 128), 256>>>(
        x, nullptr, nullptr, Wq, q_buf, 512, 512, Wkv, kv_buf, 128, 128, 8,
        nullptr, 512);

    // fused: local causal flash attention (blocks 0..127) + memory attention
    // (blocks 128..4223) overlapping tensor-core work with the HBM stream
    fused_attn_kernel<<<128 + (Bb * Hh * Nn) / 8, 256>>>(
        q_buf, kv_buf, local_buf, mem_kv, null_k, null_v, memv_buf);

    // output projection with bias; A = sigmoid(gate)-combined local/memv
    gemm_kernel<false, true><<<dim3(8, (Bb * Nn) / 128), 256>>>(
        local_buf, memv_buf, gate, Wo, out, 512, 512, Wo, out, 512, 512, 0,
        bo, 512);
}

// round 7
// speedup vs baseline: 1.9496x; 1.9496x over previous
#include <cuda_runtime.h>
#include <cuda_fp16.h>
#include <cstdint>

#define Bb 2
#define Nn 2048
#define Hh 8
#define DHd 64
#define Kk 32
#define SCALEf 0.125f
#define NEG_HUGE (-3.402823466e+38f)

// ---------------- mma / ldmatrix helpers ----------------
__device__ __forceinline__ void ldsm4(uint32_t& r0, uint32_t& r1, uint32_t& r2,
                                      uint32_t& r3, uint32_t addr) {
    asm volatile("ldmatrix.sync.aligned.m8n8.x4.shared.b16 {%0,%1,%2,%3}, [%4];"
                 : "=r"(r0), "=r"(r1), "=r"(r2), "=r"(r3) : "r"(addr));
}
__device__ __forceinline__ void ldsm4t(uint32_t& r0, uint32_t& r1, uint32_t& r2,
                                       uint32_t& r3, uint32_t addr) {
    asm volatile("ldmatrix.sync.aligned.m8n8.x4.trans.shared.b16 {%0,%1,%2,%3}, [%4];"
                 : "=r"(r0), "=r"(r1), "=r"(r2), "=r"(r3) : "r"(addr));
}
__device__ __forceinline__ void mma_f16(float* d, const uint32_t* a,
                                        uint32_t b0, uint32_t b1) {
    asm volatile(
        "mma.sync.aligned.m16n8k16.row.col.f32.f16.f16.f32 "
        "{%0,%1,%2,%3}, {%4,%5,%6,%7}, {%8,%9}, {%0,%1,%2,%3};"
        : "+f"(d[0]), "+f"(d[1]), "+f"(d[2]), "+f"(d[3])
        : "r"(a[0]), "r"(a[1]), "r"(a[2]), "r"(a[3]), "r"(b0), "r"(b1));
}
__device__ __forceinline__ uint32_t h2u(float x, float y) {
    __half2 h = __floats2half2_rn(x, y);
    return *(uint32_t*)&h;
}

// ---------------- scratch ----------------
__device__ __half g_q[Bb * Nn * (Hh * DHd)];
__device__ __half g_kv[Bb * Nn * (2 * DHd)];
__device__ float g_local[Bb * Hh * Nn * DHd];
__device__ float g_memv[Bb * Hh * Nn * DHd];
__device__ unsigned char g_mask[Bb * Hh * Nn * Kk];
__device__ int g_mask_mode;

// ---------------- mask dtype detection / expansion ----------------
__global__ void detect_mask_kernel(const unsigned int* __restrict__ raw) {
    __shared__ int cf, ch;
    if (threadIdx.x == 0) { cf = 0; ch = 0; }
    __syncthreads();
    int lf = 0, lh = 0;
    for (int idx = threadIdx.x; idx < 4096; idx += 256) {
        unsigned w = raw[idx];
        if (w == 0x3f800000u) lf++;
        if (w & 0xFFFFFF00u) lh++;
    }
    atomicAdd(&cf, lf);
    atomicAdd(&ch, lh);
    __syncthreads();
    if (threadIdx.x == 0) {
        int mode;
        if (cf > 64) mode = 2;
        else if (ch > 64) mode = 0;
        else mode = 1;
        g_mask_mode = mode;
    }
}

__global__ void expand_mask_kernel(const void* __restrict__ raw, int n) {
    int idx = blockIdx.x * blockDim.x + threadIdx.x;
    if (idx >= n) return;
    int mode = g_mask_mode;
    unsigned char v;
    if (mode == 0)      v = ((const unsigned char*)raw)[idx] != 0;
    else if (mode == 1) v = ((const int*)raw)[idx] != 0;
    else                v = (((const float*)raw)[idx] != 0.0f);
    g_mask[idx] = v;
}

// ---------------- fp16 MMA GEMM: tile 128x64, BK=32, 256 threads (8 warps) ----------------
// COMBINE: A is synthesized on the fly as gate-combined local/memv (fp32 -> fp16).
template <bool OUT_HALF, bool COMBINE>
__global__ void __launch_bounds__(256) gemm_kernel(
    const float* __restrict__ A,
    const float* __restrict__ Amem, const float* __restrict__ gatep,
    const float* __restrict__ B1, void* __restrict__ C1, int ldb1, int ldc1,
    const float* __restrict__ B2, void* __restrict__ C2, int ldb2, int ldc2,
    int nb1, const float* __restrict__ bias, int Kd)
{
    __shared__ __half As[128 * 40];  // [r][k], stride 40 halfs
    __shared__ __half Bs[32 * 72];   // [k][n], stride 72 halfs
    int tid = threadIdx.x;
    int warp = tid >> 5, lane = tid & 31;
    int lg = lane >> 2, lt = lane & 3;
    int rowBase = blockIdx.y * 128;
    const float* Bm; void* C; int ldb, ldc, colBase;
    bool hasBias;
    if ((int)blockIdx.x < nb1) {
        Bm = B1; C = C1; ldb = ldb1; ldc = ldc1; colBase = blockIdx.x * 64;
        hasBias = false;
    } else {
        Bm = B2; C = C2; ldb = ldb2; ldc = ldc2; colBase = (blockIdx.x - nb1) * 64;
        hasBias = (bias != nullptr);
    }

    uint32_t asb = (uint32_t)__cvta_generic_to_shared(As);
    uint32_t bsb = (uint32_t)__cvta_generic_to_shared(Bs);
    int a_row = (lane & 7) + (lane & 8);
    int a_cb = (lane & 16) >> 1;

    float acc[8][4];
#pragma unroll
    for (int j = 0; j < 8; j++)
#pragma unroll
        for (int q = 0; q < 4; q++) acc[j][q] = 0.f;

    int r0 = warp * 16;

    for (int k0 = 0; k0 < Kd; k0 += 32) {
        // stage A 128x32 -> fp16
#pragma unroll
        for (int rep = 0; rep < 4; rep++) {
            int r = (tid >> 3) + rep * 32;
            int kq = (tid & 7) * 4;
            float4 v;
            if (COMBINE) {
                int R = rowBase + r;
                int b = R >> 11, i = R & 2047;
                int c = k0 + kq;
                int h = c >> 6, d = c & 63;
                size_t idx = (((size_t)(b * 8 + h) * 2048 + i) * 64 + d);
                float4 lv = *(const float4*)&A[idx];
                float4 mv = *(const float4*)&Amem[idx];
                float g = 1.f / (1.f + __expf(-__ldg(&gatep[h])));
                v.x = lv.x * g + mv.x * (1.f - g);
                v.y = lv.y * g + mv.y * (1.f - g);
                v.z = lv.z * g + mv.z * (1.f - g);
                v.w = lv.w * g + mv.w * (1.f - g);
            } else {
                v = *(const float4*)&A[(size_t)(rowBase + r) * Kd + k0 + kq];
            }
            uint2 u = {h2u(v.x, v.y), h2u(v.z, v.w)};
            *(uint2*)&As[r * 40 + kq] = u;
        }
        // stage B 32x64 -> fp16
#pragma unroll
        for (int rep = 0; rep < 2; rep++) {
            int kk = (tid >> 4) + rep * 16;
            int c4 = (tid & 15) * 4;
            float4 v = *(const float4*)&Bm[(size_t)(k0 + kk) * ldb + colBase + c4];
            uint2 u = {h2u(v.x, v.y), h2u(v.z, v.w)};
            *(uint2*)&Bs[kk * 72 + c4] = u;
        }
        __syncthreads();
#pragma unroll
        for (int kc = 0; kc < 2; kc++) {
            uint32_t a[4];
            ldsm4(a[0], a[1], a[2], a[3],
                  asb + ((r0 + a_row) * 40 + kc * 16 + a_cb) * 2);
#pragma unroll
            for (int jn2 = 0; jn2 < 4; jn2++) {
                uint32_t b0, b1, b2, b3;
                ldsm4t(b0, b1, b2, b3,
                       bsb + ((kc * 16 + a_row) * 72 + jn2 * 16 + a_cb) * 2);
                mma_f16(acc[2 * jn2], a, b0, b1);
                mma_f16(acc[2 * jn2 + 1], a, b2, b3);
            }
        }
        __syncthreads();
    }

#pragma unroll
    for (int jn = 0; jn < 8; jn++) {
        int col = colBase + jn * 8 + 2 * lt;
        float b0 = 0.f, b1 = 0.f;
        if (hasBias) { b0 = bias[col]; b1 = bias[col + 1]; }
        size_t off0 = (size_t)(rowBase + r0 + lg) * ldc + col;
        size_t off1 = (size_t)(rowBase + r0 + lg + 8) * ldc + col;
        if (OUT_HALF) {
            *(__half2*)&((__half*)C)[off0] =
                __floats2half2_rn(acc[jn][0] + b0, acc[jn][1] + b1);
            *(__half2*)&((__half*)C)[off1] =
                __floats2half2_rn(acc[jn][2] + b0, acc[jn][3] + b1);
        } else {
            float2 w0 = {acc[jn][0] + b0, acc[jn][1] + b1};
            float2 w1 = {acc[jn][2] + b0, acc[jn][3] + b1};
            *(float2*)&((float*)C)[off0] = w0;
            *(float2*)&((float*)C)[off1] = w1;
        }
    }
}

// ---------------- fp16 MMA flash attention (standalone, Round-4 config) ----------------
__global__ void __launch_bounds__(256) flash_kernel(
    const __half* __restrict__ q, const __half* __restrict__ kv,
    float* __restrict__ localOut)
{
    __shared__ __half Qs[128 * 72];
    __shared__ __half Ks[64 * 72];
    __shared__ __half Vs[64 * 72];

    int tid = threadIdx.x;
    int warp = tid >> 5, lane = tid & 31;
    int lg = lane >> 2, lt = lane & 3;
    int bh = blockIdx.y, b = bh >> 3, h = bh & 7;
    int px = blockIdx.x;  // 0..7

    uint32_t qsb = (uint32_t)__cvta_generic_to_shared(Qs);
    uint32_t ksb = (uint32_t)__cvta_generic_to_shared(Ks);
    uint32_t vsb = (uint32_t)__cvta_generic_to_shared(Vs);
    int a_row = (lane & 7) + (lane & 8);
    int a_cb = (lane & 16) >> 1;
    int k_row = (lane & 7) + ((lane & 16) >> 1);
    int k_cb = (lane & 8);

    int r0 = warp * 16;

    for (int half_i = 0; half_i < 2; half_i++) {
        int qb = half_i ? (15 - px) : px;
        int i0 = qb * 128;

#pragma unroll
        for (int rep = 0; rep < 4; rep++) {
            int idx = tid + rep * 256;
            int r = idx >> 3;
            int c8 = (idx & 7) * 8;
            *(uint4*)&Qs[r * 72 + c8] =
                *(const uint4*)&q[(size_t)(b * Nn + i0 + r) * 512 + h * 64 + c8];
        }
        __syncthreads();

        uint32_t qa[4][4];
#pragma unroll
        for (int kc = 0; kc < 4; kc++)
            ldsm4(qa[kc][0], qa[kc][1], qa[kc][2], qa[kc][3],
                  qsb + ((r0 + a_row) * 72 + kc * 16 + a_cb) * 2);

        float o[8][4];
#pragma unroll
        for (int j = 0; j < 8; j++)
#pragma unroll
            for (int qq = 0; qq < 4; qq++) o[j][qq] = 0.f;
        float m_lo = NEG_HUGE, m_hi = NEG_HUGE, l_lo = 0.f, l_hi = 0.f;

        int row_lo = i0 + r0 + lg;
        int row_hi = row_lo + 8;
        int numJ = 2 * qb + 2;

        for (int jb = 0; jb < numJ; jb++) {
            int j0 = jb * 64;
            __syncthreads();
#pragma unroll
            for (int rep = 0; rep < 4; rep++) {
                int idx = tid + rep * 256;
                int c = idx >> 4;
                int q8 = (idx & 15) * 8;
                uint4 v = *(const uint4*)&kv[(size_t)(b * Nn + j0 + c) * 128 + q8];
                if (q8 < 64) *(uint4*)&Ks[c * 72 + q8] = v;
                else         *(uint4*)&Vs[c * 72 + q8 - 64] = v;
            }
            __syncthreads();

            float sacc[8][4];
#pragma unroll
            for (int j = 0; j < 8; j++)
#pragma unroll
                for (int qq = 0; qq < 4; qq++) sacc[j][qq] = 0.f;
#pragma unroll
            for (int kc = 0; kc < 4; kc++) {
#pragma unroll
                for (int jn2 = 0; jn2 < 4; jn2++) {
                    uint32_t b0, b1, b2, b3;
                    ldsm4(b0, b1, b2, b3,
                          ksb + ((jn2 * 16 + k_row) * 72 + kc * 16 + k_cb) * 2);
                    mma_f16(sacc[2 * jn2], qa[kc], b0, b1);
                    mma_f16(sacc[2 * jn2 + 1], qa[kc], b2, b3);
                }
            }

            if (jb >= 2 * qb) {
#pragma unroll
                for (int jn = 0; jn < 8; jn++) {
                    int c0 = j0 + jn * 8 + 2 * lt;
                    if (c0 > row_lo) sacc[jn][0] = NEG_HUGE;
                    if (c0 + 1 > row_lo) sacc[jn][1] = NEG_HUGE;
                    if (c0 > row_hi) sacc[jn][2] = NEG_HUGE;
                    if (c0 + 1 > row_hi) sacc[jn][3] = NEG_HUGE;
                }
            }

            float mx_lo = NEG_HUGE, mx_hi = NEG_HUGE;
#pragma unroll
            for (int jn = 0; jn < 8; jn++) {
                mx_lo = fmaxf(mx_lo, fmaxf(sacc[jn][0], sacc[jn][1]));
                mx_hi = fmaxf(mx_hi, fmaxf(sacc[jn][2], sacc[jn][3]));
            }
            mx_lo = fmaxf(mx_lo, __shfl_xor_sync(0xffffffffu, mx_lo, 1));
            mx_lo = fmaxf(mx_lo, __shfl_xor_sync(0xffffffffu, mx_lo, 2));
            mx_hi = fmaxf(mx_hi, __shfl_xor_sync(0xffffffffu, mx_hi, 1));
            mx_hi = fmaxf(mx_hi, __shfl_xor_sync(0xffffffffu, mx_hi, 2));
            float nm_lo = fmaxf(m_lo, mx_lo);
            float nm_hi = fmaxf(m_hi, mx_hi);
            float al_lo = __expf((m_lo - nm_lo) * SCALEf);
            float al_hi = __expf((m_hi - nm_hi) * SCALEf);
            m_lo = nm_lo; m_hi = nm_hi;

            uint32_t pa[4][4];
            float rs_lo = 0.f, rs_hi = 0.f;
#pragma unroll
            for (int jn = 0; jn < 8; jn++) {
                float p0 = __expf((sacc[jn][0] - nm_lo) * SCALEf);
                float p1 = __expf((sacc[jn][1] - nm_lo) * SCALEf);
                float p2 = __expf((sacc[jn][2] - nm_hi) * SCALEf);
                float p3 = __expf((sacc[jn][3] - nm_hi) * SCALEf);
                rs_lo += p0 + p1;
                rs_hi += p2 + p3;
                int kc = jn >> 1;
                int hi = (jn & 1) ? 2 : 0;
                pa[kc][hi] = h2u(p0, p1);
                pa[kc][hi + 1] = h2u(p2, p3);
                o[jn][0] *= al_lo; o[jn][1] *= al_lo;
                o[jn][2] *= al_hi; o[jn][3] *= al_hi;
            }
            rs_lo += __shfl_xor_sync(0xffffffffu, rs_lo, 1);
            rs_lo += __shfl_xor_sync(0xffffffffu, rs_lo, 2);
            rs_hi += __shfl_xor_sync(0xffffffffu, rs_hi, 1);
            rs_hi += __shfl_xor_sync(0xffffffffu, rs_hi, 2);
            l_lo = l_lo * al_lo + rs_lo;
            l_hi = l_hi * al_hi + rs_hi;

#pragma unroll
            for (int kc = 0; kc < 4; kc++) {
#pragma unroll
                for (int dn2 = 0; dn2 < 4; dn2++) {
                    uint32_t b0, b1, b2, b3;
                    ldsm4t(b0, b1, b2, b3,
                           vsb + ((kc * 16 + a_row) * 72 + dn2 * 16 + a_cb) * 2);
                    mma_f16(o[2 * dn2], pa[kc], b0, b1);
                    mma_f16(o[2 * dn2 + 1], pa[kc], b2, b3);
                }
            }
        }

        float inv_lo = 1.f / l_lo, inv_hi = 1.f / l_hi;
#pragma unroll
        for (int jn = 0; jn < 8; jn++) {
            int col = jn * 8 + 2 * lt;
            float2 w0 = {o[jn][0] * inv_lo, o[jn][1] * inv_lo};
            float2 w1 = {o[jn][2] * inv_hi, o[jn][3] * inv_hi};
            *(float2*)&localOut[((size_t)bh * Nn + row_lo) * 64 + col] = w0;
            *(float2*)&localOut[((size_t)bh * Nn + row_hi) * 64 + col] = w1;
        }
        __syncthreads();
    }
}

// ---------------- memory (KNN) attention (standalone, lightweight) ----------------
__global__ void mem_attn_kernel(const __half* __restrict__ q,
                                const float* __restrict__ memkv,
                                const float* __restrict__ nullk,
                                const float* __restrict__ nullv,
                                float* __restrict__ memvOut) {
    int gw = blockIdx.x * 8 + ((int)threadIdx.x >> 5);
    int lane = threadIdx.x & 31;
    int b = gw >> 14;
    int rem = gw & 16383;
    int h = rem >> 11;
    int i = rem & 2047;

    const __half* qp = &q[(size_t)(b * Nn + i) * 512 + h * 64];
    float q0 = __half2float(qp[lane]), q1 = __half2float(qp[lane + 32]);

    float s = q0 * __ldg(&nullk[lane]) + q1 * __ldg(&nullk[lane + 32]);
#pragma unroll
    for (int off = 16; off >= 1; off >>= 1) s += __shfl_xor_sync(0xffffffffu, s, off);
    s *= SCALEf;
    float m = s, ls = 1.f;
    float a0 = __ldg(&nullv[lane]), a1 = __ldg(&nullv[lane + 32]);

    size_t base = (size_t)(b * Hh + h) * Nn + i;
    const unsigned char* mp = &g_mask[base * Kk];
    unsigned mbits = __ballot_sync(0xffffffffu, mp[lane] != 0);
    const float* kvp = &memkv[base * (size_t)(Kk * 2 * DHd)];

    for (int kk = 0; kk < Kk; kk++) {
        if (!((mbits >> kk) & 1u)) continue;
        const float* kp = kvp + (size_t)kk * 128;
        float ss = q0 * __ldcs(&kp[lane]) + q1 * __ldcs(&kp[lane + 32]);
#pragma unroll
        for (int off = 16; off >= 1; off >>= 1) ss += __shfl_xor_sync(0xffffffffu, ss, off);
        ss *= SCALEf;
        float nm = fmaxf(m, ss);
        float al = __expf(m - nm);
        float p = __expf(ss - nm);
        m = nm;
        ls = ls * al + p;
        a0 = a0 * al + p * __ldcs(&kp[64 + lane]);
        a1 = a1 * al + p * __ldcs(&kp[96 + lane]);
    }
    float inv = 1.f / ls;
    float* mv = &memvOut[base * DHd];
    mv[lane] = a0 * inv;
    mv[lane + 32] = a1 * inv;
}

// ---------------- launch: graph with parallel flash / mem branches ----------------
extern "C" void kernel_launch(void* const* d_in, const int* in_sizes, int n_in,
                              void* d_out, int out_size) {
    const float* x      = (const float*)d_in[0];
    const float* mem_kv = (const float*)d_in[1];
    const void*  m_mask = d_in[2];
    const float* Wq     = (const float*)d_in[3];
    const float* Wkv    = (const float*)d_in[4];
    const float* Wo     = (const float*)d_in[5];
    const float* bo     = (const float*)d_in[6];
    const float* null_k = (const float*)d_in[7];
    const float* null_v = (const float*)d_in[8];
    const float* gate   = (const float*)d_in[9];
    float* out = (float*)d_out;

    __half* q_buf;    cudaGetSymbolAddress((void**)&q_buf, g_q);
    __half* kv_buf;   cudaGetSymbolAddress((void**)&kv_buf, g_kv);
    float* local_buf; cudaGetSymbolAddress((void**)&local_buf, g_local);
    float* memv_buf;  cudaGetSymbolAddress((void**)&memv_buf, g_memv);

    // side stream + fork/join events (host objects only; created per call —
    // kernel_launch runs only for the correctness pass and graph capture)
    cudaStream_t sB;
    cudaStreamCreateWithFlags(&sB, cudaStreamNonBlocking);
    cudaEvent_t evFork, evJoin;
    cudaEventCreateWithFlags(&evFork, cudaEventDisableTiming);
    cudaEventCreateWithFlags(&evJoin, cudaEventDisableTiming);

    // side branch: mask prep (independent of gemm1)
    detect_mask_kernel<<<1, 256, 0, sB>>>((const unsigned int*)m_mask);
    expand_mask_kernel<<<(Bb * Hh * Nn * Kk + 255) / 256, 256, 0, sB>>>(
        m_mask, Bb * Hh * Nn * Kk);

    // main: fused q + kv projection (fp16 out)
    gemm_kernel<true, false><<<dim3(10, (Bb * Nn) / 128), 256>>>(
        x, nullptr, nullptr, Wq, q_buf, 512, 512, Wkv, kv_buf, 128, 128, 8,
        nullptr, 512);

    // fork: mem branch waits for q_buf
    cudaEventRecord(evFork, 0);
    cudaStreamWaitEvent(sB, evFork, 0);

    // parallel: flash (tensor pipe, stream 0) || mem attention (HBM, stream B)
    flash_kernel<<<dim3(8, Bb * Hh), 256>>>(q_buf, kv_buf, local_buf);
    mem_attn_kernel<<<(Bb * Hh * Nn) / 8, 256, 0, sB>>>(
        q_buf, mem_kv, null_k, null_v, memv_buf);

    // join
    cudaEventRecord(evJoin, sB);
    cudaStreamWaitEvent(0, evJoin, 0);

    // output projection; A = sigmoid(gate)-combined local/memv
    gemm_kernel<false, true><<<dim3(8, (Bb * Nn) / 128), 256>>>(
        local_buf, memv_buf, gate, Wo, out, 512, 512, Wo, out, 512, 512, 0,
        bo, 512);
}

// round 8
// speedup vs baseline: 2.0299x; 1.0412x over previous
#include <cuda_runtime.h>
#include <cuda_fp16.h>
#include <cstdint>

#define Bb 2
#define Nn 2048
#define Hh 8
#define DHd 64
#define Kk 32
#define SCALEf 0.125f
#define NEG_HUGE (-3.402823466e+38f)

// ---------------- mma / ldmatrix helpers ----------------
__device__ __forceinline__ void ldsm4(uint32_t& r0, uint32_t& r1, uint32_t& r2,
                                      uint32_t& r3, uint32_t addr) {
    asm volatile("ldmatrix.sync.aligned.m8n8.x4.shared.b16 {%0,%1,%2,%3}, [%4];"
                 : "=r"(r0), "=r"(r1), "=r"(r2), "=r"(r3) : "r"(addr));
}
__device__ __forceinline__ void ldsm4t(uint32_t& r0, uint32_t& r1, uint32_t& r2,
                                       uint32_t& r3, uint32_t addr) {
    asm volatile("ldmatrix.sync.aligned.m8n8.x4.trans.shared.b16 {%0,%1,%2,%3}, [%4];"
                 : "=r"(r0), "=r"(r1), "=r"(r2), "=r"(r3) : "r"(addr));
}
__device__ __forceinline__ void mma_f16(float* d, const uint32_t* a,
                                        uint32_t b0, uint32_t b1) {
    asm volatile(
        "mma.sync.aligned.m16n8k16.row.col.f32.f16.f16.f32 "
        "{%0,%1,%2,%3}, {%4,%5,%6,%7}, {%8,%9}, {%0,%1,%2,%3};"
        : "+f"(d[0]), "+f"(d[1]), "+f"(d[2]), "+f"(d[3])
        : "r"(a[0]), "r"(a[1]), "r"(a[2]), "r"(a[3]), "r"(b0), "r"(b1));
}
__device__ __forceinline__ uint32_t h2u(float x, float y) {
    __half2 h = __floats2half2_rn(x, y);
    return *(uint32_t*)&h;
}

// ---------------- scratch ----------------
__device__ __half g_q[Bb * Nn * (Hh * DHd)];
__device__ __half g_kv[Bb * Nn * (2 * DHd)];
__device__ float g_local[Bb * Hh * Nn * DHd];
__device__ float g_memv[Bb * Hh * Nn * DHd];
__device__ unsigned char g_mask[Bb * Hh * Nn * Kk];
__device__ int g_mask_mode;

// ---------------- mask dtype detection / expansion ----------------
__global__ void detect_mask_kernel(const unsigned int* __restrict__ raw) {
    __shared__ int cf, ch;
    if (threadIdx.x == 0) { cf = 0; ch = 0; }
    __syncthreads();
    int lf = 0, lh = 0;
    for (int idx = threadIdx.x; idx < 4096; idx += 256) {
        unsigned w = raw[idx];
        if (w == 0x3f800000u) lf++;
        if (w & 0xFFFFFF00u) lh++;
    }
    atomicAdd(&cf, lf);
    atomicAdd(&ch, lh);
    __syncthreads();
    if (threadIdx.x == 0) {
        int mode;
        if (cf > 64) mode = 2;
        else if (ch > 64) mode = 0;
        else mode = 1;
        g_mask_mode = mode;
    }
}

__global__ void expand_mask_kernel(const void* __restrict__ raw, int n) {
    int idx = blockIdx.x * blockDim.x + threadIdx.x;
    if (idx >= n) return;
    int mode = g_mask_mode;
    unsigned char v;
    if (mode == 0)      v = ((const unsigned char*)raw)[idx] != 0;
    else if (mode == 1) v = ((const int*)raw)[idx] != 0;
    else                v = (((const float*)raw)[idx] != 0.0f);
    g_mask[idx] = v;
}

// ---------------- fp16 MMA GEMM (register-prefetch pipelined) ----------------
// tile 128x64, BK=32, 256 threads. COMBINE: A synthesized as gated local/memv.
template <bool OUT_HALF, bool COMBINE>
__global__ void __launch_bounds__(256) gemm_kernel(
    const float* __restrict__ A,
    const float* __restrict__ Amem, const float* __restrict__ gatep,
    const float* __restrict__ B1, void* __restrict__ C1, int ldb1, int ldc1,
    const float* __restrict__ B2, void* __restrict__ C2, int ldb2, int ldc2,
    int nb1, const float* __restrict__ bias, int Kd)
{
    __shared__ __half As[128 * 40];
    __shared__ __half Bs[32 * 72];
    int tid = threadIdx.x;
    int warp = tid >> 5, lane = tid & 31;
    int lg = lane >> 2, lt = lane & 3;
    int rowBase = blockIdx.y * 128;
    const float* Bm; void* C; int ldb, ldc, colBase;
    bool hasBias;
    if ((int)blockIdx.x < nb1) {
        Bm = B1; C = C1; ldb = ldb1; ldc = ldc1; colBase = blockIdx.x * 64;
        hasBias = false;
    } else {
        Bm = B2; C = C2; ldb = ldb2; ldc = ldc2; colBase = (blockIdx.x - nb1) * 64;
        hasBias = (bias != nullptr);
    }

    uint32_t asb = (uint32_t)__cvta_generic_to_shared(As);
    uint32_t bsb = (uint32_t)__cvta_generic_to_shared(Bs);
    int a_row = (lane & 7) + (lane & 8);
    int a_cb = (lane & 16) >> 1;

    int ar = tid >> 3;          // A stage row base (+=32 per rep)
    int akq = (tid & 7) * 4;
    int bk = tid >> 4;          // B stage k base (+=16 per rep)
    int bc4 = (tid & 15) * 4;

    float4 pfA[4];
    float4 pfB[2];

    // prefetch loader
    auto loadA = [&](int k0) {
#pragma unroll
        for (int rep = 0; rep < 4; rep++) {
            int r = ar + rep * 32;
            if (COMBINE) {
                int R = rowBase + r;
                int b = R >> 11, i = R & 2047;
                int c = k0 + akq;
                int h = c >> 6, d = c & 63;
                size_t idx = (((size_t)(b * 8 + h) * 2048 + i) * 64 + d);
                float4 lv = *(const float4*)&A[idx];
                float4 mv = *(const float4*)&Amem[idx];
                float g = 1.f / (1.f + __expf(-__ldg(&gatep[h])));
                pfA[rep].x = lv.x * g + mv.x * (1.f - g);
                pfA[rep].y = lv.y * g + mv.y * (1.f - g);
                pfA[rep].z = lv.z * g + mv.z * (1.f - g);
                pfA[rep].w = lv.w * g + mv.w * (1.f - g);
            } else {
                pfA[rep] = *(const float4*)&A[(size_t)(rowBase + r) * Kd + k0 + akq];
            }
        }
    };
    auto loadB = [&](int k0) {
#pragma unroll
        for (int rep = 0; rep < 2; rep++) {
            int kk = bk + rep * 16;
            pfB[rep] = *(const float4*)&Bm[(size_t)(k0 + kk) * ldb + colBase + bc4];
        }
    };

    float acc[8][4];
#pragma unroll
    for (int j = 0; j < 8; j++)
#pragma unroll
        for (int q = 0; q < 4; q++) acc[j][q] = 0.f;

    int r0 = warp * 16;

    loadA(0);
    loadB(0);

    for (int k0 = 0; k0 < Kd; k0 += 32) {
        // STS current (fp32 regs -> fp16 smem)
#pragma unroll
        for (int rep = 0; rep < 4; rep++) {
            uint2 u = {h2u(pfA[rep].x, pfA[rep].y), h2u(pfA[rep].z, pfA[rep].w)};
            *(uint2*)&As[(ar + rep * 32) * 40 + akq] = u;
        }
#pragma unroll
        for (int rep = 0; rep < 2; rep++) {
            uint2 u = {h2u(pfB[rep].x, pfB[rep].y), h2u(pfB[rep].z, pfB[rep].w)};
            *(uint2*)&Bs[(bk + rep * 16) * 72 + bc4] = u;
        }
        __syncthreads();
        // issue next tile's loads (latency hidden under mma)
        if (k0 + 32 < Kd) { loadA(k0 + 32); loadB(k0 + 32); }
#pragma unroll
        for (int kc = 0; kc < 2; kc++) {
            uint32_t a[4];
            ldsm4(a[0], a[1], a[2], a[3],
                  asb + ((r0 + a_row) * 40 + kc * 16 + a_cb) * 2);
#pragma unroll
            for (int jn2 = 0; jn2 < 4; jn2++) {
                uint32_t b0, b1, b2, b3;
                ldsm4t(b0, b1, b2, b3,
                       bsb + ((kc * 16 + a_row) * 72 + jn2 * 16 + a_cb) * 2);
                mma_f16(acc[2 * jn2], a, b0, b1);
                mma_f16(acc[2 * jn2 + 1], a, b2, b3);
            }
        }
        __syncthreads();
    }

#pragma unroll
    for (int jn = 0; jn < 8; jn++) {
        int col = colBase + jn * 8 + 2 * lt;
        float b0 = 0.f, b1 = 0.f;
        if (hasBias) { b0 = bias[col]; b1 = bias[col + 1]; }
        size_t off0 = (size_t)(rowBase + r0 + lg) * ldc + col;
        size_t off1 = (size_t)(rowBase + r0 + lg + 8) * ldc + col;
        if (OUT_HALF) {
            *(__half2*)&((__half*)C)[off0] =
                __floats2half2_rn(acc[jn][0] + b0, acc[jn][1] + b1);
            *(__half2*)&((__half*)C)[off1] =
                __floats2half2_rn(acc[jn][2] + b0, acc[jn][3] + b1);
        } else {
            float2 w0 = {acc[jn][0] + b0, acc[jn][1] + b1};
            float2 w1 = {acc[jn][2] + b0, acc[jn][3] + b1};
            *(float2*)&((float*)C)[off0] = w0;
            *(float2*)&((float*)C)[off1] = w1;
        }
    }
}

// ---------------- fp16 MMA flash attention (K/V register-prefetch) ----------------
__global__ void __launch_bounds__(256) flash_kernel(
    const __half* __restrict__ q, const __half* __restrict__ kv,
    float* __restrict__ localOut)
{
    __shared__ __half Qs[128 * 72];
    __shared__ __half Ks[64 * 72];
    __shared__ __half Vs[64 * 72];

    int tid = threadIdx.x;
    int warp = tid >> 5, lane = tid & 31;
    int lg = lane >> 2, lt = lane & 3;
    int bh = blockIdx.y, b = bh >> 3, h = bh & 7;
    int px = blockIdx.x;  // 0..7

    uint32_t qsb = (uint32_t)__cvta_generic_to_shared(Qs);
    uint32_t ksb = (uint32_t)__cvta_generic_to_shared(Ks);
    uint32_t vsb = (uint32_t)__cvta_generic_to_shared(Vs);
    int a_row = (lane & 7) + (lane & 8);
    int a_cb = (lane & 16) >> 1;
    int k_row = (lane & 7) + ((lane & 16) >> 1);
    int k_cb = (lane & 8);

    int r0 = warp * 16;

    // K/V staging indices: idx = tid + rep*256 -> row c = idx>>4, col q8 = (idx&15)*8
    int kvc = tid >> 4;
    int kvq8 = (tid & 15) * 8;
    uint4 pfKV[4];
    auto loadKV = [&](int j0) {
#pragma unroll
        for (int rep = 0; rep < 4; rep++) {
            int c = kvc + rep * 16;
            pfKV[rep] = *(const uint4*)&kv[(size_t)(b * Nn + j0 + c) * 128 + kvq8];
        }
    };

    for (int half_i = 0; half_i < 2; half_i++) {
        int qb = half_i ? (15 - px) : px;
        int i0 = qb * 128;

#pragma unroll
        for (int rep = 0; rep < 4; rep++) {
            int idx = tid + rep * 256;
            int r = idx >> 3;
            int c8 = (idx & 7) * 8;
            *(uint4*)&Qs[r * 72 + c8] =
                *(const uint4*)&q[(size_t)(b * Nn + i0 + r) * 512 + h * 64 + c8];
        }
        loadKV(0);
        __syncthreads();

        uint32_t qa[4][4];
#pragma unroll
        for (int kc = 0; kc < 4; kc++)
            ldsm4(qa[kc][0], qa[kc][1], qa[kc][2], qa[kc][3],
                  qsb + ((r0 + a_row) * 72 + kc * 16 + a_cb) * 2);

        float o[8][4];
#pragma unroll
        for (int j = 0; j < 8; j++)
#pragma unroll
            for (int qq = 0; qq < 4; qq++) o[j][qq] = 0.f;
        float m_lo = NEG_HUGE, m_hi = NEG_HUGE, l_lo = 0.f, l_hi = 0.f;

        int row_lo = i0 + r0 + lg;
        int row_hi = row_lo + 8;
        int numJ = 2 * qb + 2;

        for (int jb = 0; jb < numJ; jb++) {
            int j0 = jb * 64;
            // STS prefetched K/V
#pragma unroll
            for (int rep = 0; rep < 4; rep++) {
                int c = kvc + rep * 16;
                if (kvq8 < 64) *(uint4*)&Ks[c * 72 + kvq8] = pfKV[rep];
                else           *(uint4*)&Vs[c * 72 + kvq8 - 64] = pfKV[rep];
            }
            __syncthreads();
            // prefetch next tile (hidden under S/softmax/PV)
            if (jb + 1 < numJ) loadKV(j0 + 64);

            float sacc[8][4];
#pragma unroll
            for (int j = 0; j < 8; j++)
#pragma unroll
                for (int qq = 0; qq < 4; qq++) sacc[j][qq] = 0.f;
#pragma unroll
            for (int kc = 0; kc < 4; kc++) {
#pragma unroll
                for (int jn2 = 0; jn2 < 4; jn2++) {
                    uint32_t b0, b1, b2, b3;
                    ldsm4(b0, b1, b2, b3,
                          ksb + ((jn2 * 16 + k_row) * 72 + kc * 16 + k_cb) * 2);
                    mma_f16(sacc[2 * jn2], qa[kc], b0, b1);
                    mma_f16(sacc[2 * jn2 + 1], qa[kc], b2, b3);
                }
            }

            if (jb >= 2 * qb) {
#pragma unroll
                for (int jn = 0; jn < 8; jn++) {
                    int c0 = j0 + jn * 8 + 2 * lt;
                    if (c0 > row_lo) sacc[jn][0] = NEG_HUGE;
                    if (c0 + 1 > row_lo) sacc[jn][1] = NEG_HUGE;
                    if (c0 > row_hi) sacc[jn][2] = NEG_HUGE;
                    if (c0 + 1 > row_hi) sacc[jn][3] = NEG_HUGE;
                }
            }

            float mx_lo = NEG_HUGE, mx_hi = NEG_HUGE;
#pragma unroll
            for (int jn = 0; jn < 8; jn++) {
                mx_lo = fmaxf(mx_lo, fmaxf(sacc[jn][0], sacc[jn][1]));
                mx_hi = fmaxf(mx_hi, fmaxf(sacc[jn][2], sacc[jn][3]));
            }
            mx_lo = fmaxf(mx_lo, __shfl_xor_sync(0xffffffffu, mx_lo, 1));
            mx_lo = fmaxf(mx_lo, __shfl_xor_sync(0xffffffffu, mx_lo, 2));
            mx_hi = fmaxf(mx_hi, __shfl_xor_sync(0xffffffffu, mx_hi, 1));
            mx_hi = fmaxf(mx_hi, __shfl_xor_sync(0xffffffffu, mx_hi, 2));
            float nm_lo = fmaxf(m_lo, mx_lo);
            float nm_hi = fmaxf(m_hi, mx_hi);
            float al_lo = __expf((m_lo - nm_lo) * SCALEf);
            float al_hi = __expf((m_hi - nm_hi) * SCALEf);
            m_lo = nm_lo; m_hi = nm_hi;

            uint32_t pa[4][4];
            float rs_lo = 0.f, rs_hi = 0.f;
#pragma unroll
            for (int jn = 0; jn < 8; jn++) {
                float p0 = __expf((sacc[jn][0] - nm_lo) * SCALEf);
                float p1 = __expf((sacc[jn][1] - nm_lo) * SCALEf);
                float p2 = __expf((sacc[jn][2] - nm_hi) * SCALEf);
                float p3 = __expf((sacc[jn][3] - nm_hi) * SCALEf);
                rs_lo += p0 + p1;
                rs_hi += p2 + p3;
                int kc = jn >> 1;
                int hi = (jn & 1) ? 2 : 0;
                pa[kc][hi] = h2u(p0, p1);
                pa[kc][hi + 1] = h2u(p2, p3);
                o[jn][0] *= al_lo; o[jn][1] *= al_lo;
                o[jn][2] *= al_hi; o[jn][3] *= al_hi;
            }
            rs_lo += __shfl_xor_sync(0xffffffffu, rs_lo, 1);
            rs_lo += __shfl_xor_sync(0xffffffffu, rs_lo, 2);
            rs_hi += __shfl_xor_sync(0xffffffffu, rs_hi, 1);
            rs_hi += __shfl_xor_sync(0xffffffffu, rs_hi, 2);
            l_lo = l_lo * al_lo + rs_lo;
            l_hi = l_hi * al_hi + rs_hi;

#pragma unroll
            for (int kc = 0; kc < 4; kc++) {
#pragma unroll
                for (int dn2 = 0; dn2 < 4; dn2++) {
                    uint32_t b0, b1, b2, b3;
                    ldsm4t(b0, b1, b2, b3,
                           vsb + ((kc * 16 + a_row) * 72 + dn2 * 16 + a_cb) * 2);
                    mma_f16(o[2 * dn2], pa[kc], b0, b1);
                    mma_f16(o[2 * dn2 + 1], pa[kc], b2, b3);
                }
            }
            __syncthreads();  // all warps done with Ks/Vs before next STS
        }

        float inv_lo = 1.f / l_lo, inv_hi = 1.f / l_hi;
#pragma unroll
        for (int jn = 0; jn < 8; jn++) {
            int col = jn * 8 + 2 * lt;
            float2 w0 = {o[jn][0] * inv_lo, o[jn][1] * inv_lo};
            float2 w1 = {o[jn][2] * inv_hi, o[jn][3] * inv_hi};
            *(float2*)&localOut[((size_t)bh * Nn + row_lo) * 64 + col] = w0;
            *(float2*)&localOut[((size_t)bh * Nn + row_hi) * 64 + col] = w1;
        }
        __syncthreads();  // protect Qs before next half re-stages
    }
}

// ---------------- memory (KNN) attention (standalone, lightweight) ----------------
__global__ void mem_attn_kernel(const __half* __restrict__ q,
                                const float* __restrict__ memkv,
                                const float* __restrict__ nullk,
                                const float* __restrict__ nullv,
                                float* __restrict__ memvOut) {
    int gw = blockIdx.x * 8 + ((int)threadIdx.x >> 5);
    int lane = threadIdx.x & 31;
    int b = gw >> 14;
    int rem = gw & 16383;
    int h = rem >> 11;
    int i = rem & 2047;

    const __half* qp = &q[(size_t)(b * Nn + i) * 512 + h * 64];
    float q0 = __half2float(qp[lane]), q1 = __half2float(qp[lane + 32]);

    float s = q0 * __ldg(&nullk[lane]) + q1 * __ldg(&nullk[lane + 32]);
#pragma unroll
    for (int off = 16; off >= 1; off >>= 1) s += __shfl_xor_sync(0xffffffffu, s, off);
    s *= SCALEf;
    float m = s, ls = 1.f;
    float a0 = __ldg(&nullv[lane]), a1 = __ldg(&nullv[lane + 32]);

    size_t base = (size_t)(b * Hh + h) * Nn + i;
    const unsigned char* mp = &g_mask[base * Kk];
    unsigned mbits = __ballot_sync(0xffffffffu, mp[lane] != 0);
    const float* kvp = &memkv[base * (size_t)(Kk * 2 * DHd)];

    for (int kk = 0; kk < Kk; kk++) {
        if (!((mbits >> kk) & 1u)) continue;
        const float* kp = kvp + (size_t)kk * 128;
        float ss = q0 * __ldcs(&kp[lane]) + q1 * __ldcs(&kp[lane + 32]);
#pragma unroll
        for (int off = 16; off >= 1; off >>= 1) ss += __shfl_xor_sync(0xffffffffu, ss, off);
        ss *= SCALEf;
        float nm = fmaxf(m, ss);
        float al = __expf(m - nm);
        float p = __expf(ss - nm);
        m = nm;
        ls = ls * al + p;
        a0 = a0 * al + p * __ldcs(&kp[64 + lane]);
        a1 = a1 * al + p * __ldcs(&kp[96 + lane]);
    }
    float inv = 1.f / ls;
    float* mv = &memvOut[base * DHd];
    mv[lane] = a0 * inv;
    mv[lane + 32] = a1 * inv;
}

// ---------------- launch: graph with parallel flash / mem branches ----------------
extern "C" void kernel_launch(void* const* d_in, const int* in_sizes, int n_in,
                              void* d_out, int out_size) {
    const float* x      = (const float*)d_in[0];
    const float* mem_kv = (const float*)d_in[1];
    const void*  m_mask = d_in[2];
    const float* Wq     = (const float*)d_in[3];
    const float* Wkv    = (const float*)d_in[4];
    const float* Wo     = (const float*)d_in[5];
    const float* bo     = (const float*)d_in[6];
    const float* null_k = (const float*)d_in[7];
    const float* null_v = (const float*)d_in[8];
    const float* gate   = (const float*)d_in[9];
    float* out = (float*)d_out;

    __half* q_buf;    cudaGetSymbolAddress((void**)&q_buf, g_q);
    __half* kv_buf;   cudaGetSymbolAddress((void**)&kv_buf, g_kv);
    float* local_buf; cudaGetSymbolAddress((void**)&local_buf, g_local);
    float* memv_buf;  cudaGetSymbolAddress((void**)&memv_buf, g_memv);

    cudaStream_t sB;
    cudaStreamCreateWithFlags(&sB, cudaStreamNonBlocking);
    cudaEvent_t evFork, evJoin;
    cudaEventCreateWithFlags(&evFork, cudaEventDisableTiming);
    cudaEventCreateWithFlags(&evJoin, cudaEventDisableTiming);

    // side branch: mask prep (independent of gemm1)
    detect_mask_kernel<<<1, 256, 0, sB>>>((const unsigned int*)m_mask);
    expand_mask_kernel<<<(Bb * Hh * Nn * Kk + 255) / 256, 256, 0, sB>>>(
        m_mask, Bb * Hh * Nn * Kk);

    // main: fused q + kv projection (fp16 out)
    gemm_kernel<true, false><<<dim3(10, (Bb * Nn) / 128), 256>>>(
        x, nullptr, nullptr, Wq, q_buf, 512, 512, Wkv, kv_buf, 128, 128, 8,
        nullptr, 512);

    // fork: mem branch waits for q_buf
    cudaEventRecord(evFork, 0);
    cudaStreamWaitEvent(sB, evFork, 0);

    // parallel: flash (tensor pipe, stream 0) || mem attention (HBM, stream B)
    flash_kernel<<<dim3(8, Bb * Hh), 256>>>(q_buf, kv_buf, local_buf);
    mem_attn_kernel<<<(Bb * Hh * Nn) / 8, 256, 0, sB>>>(
        q_buf, mem_kv, null_k, null_v, memv_buf);

    // join
    cudaEventRecord(evJoin, sB);
    cudaStreamWaitEvent(0, evJoin, 0);

    // output projection; A = sigmoid(gate)-combined local/memv
    gemm_kernel<false, true><<<dim3(8, (Bb * Nn) / 128), 256>>>(
        local_buf, memv_buf, gate, Wo, out, 512, 512, Wo, out, 512, 512, 0,
        bo, 512);
}